// round 1
// baseline (speedup 1.0000x reference)
#include <cuda_runtime.h>
#include <math.h>

#define BN   8
#define HH   512
#define WW   1024
#define GG   104857
#define NTOT (BN * GG)   // 838856

// ---------------- device scratch (no allocations allowed) ----------------
__device__ float        g_loss[NTOT];
__device__ double       g_sum_valid;
__device__ unsigned int g_n;
__device__ unsigned int g_hist[256];
__device__ unsigned int g_prefix;
__device__ unsigned int g_krem;
__device__ double       g_sum_less;
__device__ unsigned int g_count_less;

// ---------------- init ----------------
__global__ void init_kernel() {
    int t = threadIdx.x;
    g_hist[t] = 0u;
    if (t == 0) {
        g_sum_valid  = 0.0;
        g_n          = 0u;
        g_prefix     = 0u;
        g_krem       = 0u;
        g_sum_less   = 0.0;
        g_count_less = 0u;
    }
}

// ---------------- main compute: loss per group + pass-1 histogram ----------------
__global__ void __launch_bounds__(256)
compute_kernel(const float* __restrict__ pred,
               const float* __restrict__ tgt,
               const float* __restrict__ intr,
               const int*   __restrict__ p1,
               const int*   __restrict__ p2,
               const int*   __restrict__ p3)
{
    __shared__ unsigned int sh_hist[256];
    __shared__ float        sh_sum[8];
    __shared__ unsigned int sh_cnt[8];

    for (int t = threadIdx.x; t < 256; t += blockDim.x) sh_hist[t] = 0u;
    __syncthreads();

    const float EPS   = 1e-6f;
    const float DCOS  = 0.867f;
    const float DDIFF = 0.005f;
    const float DZ    = 1e-5f;
    const float INF_F = __int_as_float(0x7f800000);

    float        local_sum = 0.0f;
    unsigned int local_cnt = 0u;

    for (int i = blockIdx.x * blockDim.x + threadIdx.x; i < NTOT;
         i += gridDim.x * blockDim.x)
    {
        int b = i / GG;
        const float* tb = tgt  + b * (HH * WW);
        const float* pb = pred + b * (HH * WW);
        float f    = __ldg(intr + b * 9 + 0);
        float u0   = __ldg(intr + b * 9 + 2);
        float v0   = __ldg(intr + b * 9 + 5);
        float invf = 1.0f / f;

        int id0 = __ldg(p1 + i);
        int id1 = __ldg(p2 + i);
        int id2 = __ldg(p3 + i);

        float Px[3], Py[3], Pz[3], Qx[3], Qy[3], Qz[3];
        int ids[3] = {id0, id1, id2};
        #pragma unroll
        for (int j = 0; j < 3; j++) {
            int id  = ids[j];
            float u = (float)(id & (WW - 1)) - u0;
            float v = (float)(id >> 10)      - v0;
            float dt = __ldg(tb + id);
            float dp = __ldg(pb + id);
            Px[j] = u * dt * invf;  Py[j] = v * dt * invf;  Pz[j] = dt;
            Qx[j] = u * dp * invf;  Qy[j] = v * dp * invf;  Qz[j] = dp;
        }

        // GT diffs: D0 = p2-p1, D1 = p3-p1, D2 = p3-p2
        float Dx[3], Dy[3], Dz[3];
        Dx[0] = Px[1] - Px[0]; Dy[0] = Py[1] - Py[0]; Dz[0] = Pz[1] - Pz[0];
        Dx[1] = Px[2] - Px[0]; Dy[1] = Py[2] - Py[0]; Dz[1] = Pz[2] - Pz[0];
        Dx[2] = Px[2] - Px[1]; Dy[2] = Py[2] - Py[1]; Dz[2] = Pz[2] - Pz[1];

        // Gram matrix of diffs (symmetric)
        float e00 = Dx[0]*Dx[0] + Dy[0]*Dy[0] + Dz[0]*Dz[0];
        float e11 = Dx[1]*Dx[1] + Dy[1]*Dy[1] + Dz[1]*Dz[1];
        float e22 = Dx[2]*Dx[2] + Dy[2]*Dy[2] + Dz[2]*Dz[2];
        float e01 = Dx[0]*Dx[1] + Dy[0]*Dy[1] + Dz[0]*Dz[1];
        float e02 = Dx[0]*Dx[2] + Dy[0]*Dy[2] + Dz[0]*Dz[2];
        float e12 = Dx[1]*Dx[2] + Dy[1]*Dy[2] + Dz[1]*Dz[2];

        float qn0 = sqrtf(e00), qn1 = sqrtf(e11), qn2 = sqrtf(e22);

        // |e/(qn_i*qn_j + EPS)| > DCOS  <=>  |e| > DCOS*(qn_i*qn_j + EPS)
        int cnt = 0;
        cnt += (fabsf(e00) > DCOS * (qn0 * qn0 + EPS)) ? 1 : 0;
        cnt += (fabsf(e11) > DCOS * (qn1 * qn1 + EPS)) ? 1 : 0;
        cnt += (fabsf(e22) > DCOS * (qn2 * qn2 + EPS)) ? 1 : 0;
        cnt += (fabsf(e01) > DCOS * (qn0 * qn1 + EPS)) ? 2 : 0;
        cnt += (fabsf(e02) > DCOS * (qn0 * qn2 + EPS)) ? 2 : 0;
        cnt += (fabsf(e12) > DCOS * (qn1 * qn2 + EPS)) ? 2 : 0;
        bool mask_cos = cnt > 3;

        bool mask_pad = (Pz[0] > DZ) && (Pz[1] > DZ) && (Pz[2] > DZ);
        bool mx = (fabsf(Dx[0]) < DDIFF) || (fabsf(Dx[1]) < DDIFF) || (fabsf(Dx[2]) < DDIFF);
        bool my = (fabsf(Dy[0]) < DDIFF) || (fabsf(Dy[1]) < DDIFF) || (fabsf(Dy[2]) < DDIFF);
        bool mz = (fabsf(Dz[0]) < DDIFF) || (fabsf(Dz[1]) < DDIFF) || (fabsf(Dz[2]) < DDIFF);
        bool valid = mask_pad && !((mx && my && mz) || mask_cos);

        // faithful replication of pred_g[pred_g[:,:,2,:]==0] = 1e-4 broadcast quirk:
        // z of point j == 0  =>  coord j of ALL points := 1e-4
        bool c0 = (Qz[0] == 0.0f), c1 = (Qz[1] == 0.0f), c2 = (Qz[2] == 0.0f);
        if (c0) { Qx[0] = 1e-4f; Qx[1] = 1e-4f; Qx[2] = 1e-4f; }
        if (c1) { Qy[0] = 1e-4f; Qy[1] = 1e-4f; Qy[2] = 1e-4f; }
        if (c2) { Qz[0] = 1e-4f; Qz[1] = 1e-4f; Qz[2] = 1e-4f; }

        // GT normal: cross(D0, D1)
        float ngx = Dy[0] * Dz[1] - Dz[0] * Dy[1];
        float ngy = Dz[0] * Dx[1] - Dx[0] * Dz[1];
        float ngz = Dx[0] * Dy[1] - Dy[0] * Dx[1];
        float sg  = ngx * ngx + ngy * ngy + ngz * ngz;
        float nng = sqrtf(sg);
        if (nng == 0.0f) nng = EPS;
        float ig = 1.0f / nng;
        ngx *= ig; ngy *= ig; ngz *= ig;

        // pred normal
        float ax = Qx[1] - Qx[0], ay = Qy[1] - Qy[0], az = Qz[1] - Qz[0];
        float bx = Qx[2] - Qx[0], by = Qy[2] - Qy[0], bz = Qz[2] - Qz[0];
        float npx = ay * bz - az * by;
        float npy = az * bx - ax * bz;
        float npz = ax * by - ay * bx;
        float sp  = npx * npx + npy * npy + npz * npz;
        float nnp = sqrtf(sp);
        if (nnp == 0.0f) nnp = EPS;
        float ip = 1.0f / nnp;
        npx *= ip; npy *= ip; npz *= ip;

        float loss = fabsf(ngx - npx) + fabsf(ngy - npy) + fabsf(ngz - npz);

        float out = valid ? loss : INF_F;   // +inf sinks past all finite values
        g_loss[i] = out;
        if (valid) { local_sum += loss; local_cnt++; }
        atomicAdd(&sh_hist[__float_as_uint(out) >> 24], 1u);
    }

    // block reduction of sum / count
    float        s = local_sum;
    unsigned int c = local_cnt;
    #pragma unroll
    for (int o = 16; o > 0; o >>= 1) {
        s += __shfl_down_sync(0xffffffffu, s, o);
        c += __shfl_down_sync(0xffffffffu, c, o);
    }
    int wid = threadIdx.x >> 5, lid = threadIdx.x & 31;
    if (lid == 0) { sh_sum[wid] = s; sh_cnt[wid] = c; }
    __syncthreads();
    if (threadIdx.x == 0) {
        float ts = 0.0f; unsigned int tc = 0u;
        #pragma unroll
        for (int w = 0; w < 8; w++) { ts += sh_sum[w]; tc += sh_cnt[w]; }
        atomicAdd(&g_sum_valid, (double)ts);
        atomicAdd(&g_n, tc);
    }
    // merge pass-1 histogram
    for (int t = threadIdx.x; t < 256; t += blockDim.x) {
        unsigned int h = sh_hist[t];
        if (h) atomicAdd(&g_hist[t], h);
    }
}

// ---------------- radix-select histogram passes 2..4 ----------------
__global__ void __launch_bounds__(256)
hist_pass_kernel(int shift)
{
    __shared__ unsigned int sh[256];
    for (int t = threadIdx.x; t < 256; t += blockDim.x) sh[t] = 0u;
    __syncthreads();

    unsigned int prefix = g_prefix;
    unsigned int mask   = 0xFFFFFFFFu << (shift + 8);

    for (int i = blockIdx.x * blockDim.x + threadIdx.x; i < NTOT;
         i += gridDim.x * blockDim.x)
    {
        unsigned int bits = __float_as_uint(g_loss[i]);
        if ((bits & mask) == prefix)
            atomicAdd(&sh[(bits >> shift) & 0xFFu], 1u);
    }
    __syncthreads();
    for (int t = threadIdx.x; t < 256; t += blockDim.x) {
        unsigned int h = sh[t];
        if (h) atomicAdd(&g_hist[t], h);
    }
}

// ---------------- resolve: pick bucket holding k-th smallest, reset hist ----------------
__global__ void resolve_kernel(int shift, int first)
{
    if (threadIdx.x == 0) {
        unsigned int k = first ? (g_n >> 2) : g_krem;   // k = n // 4
        unsigned int cum = 0u, sel = 0u, krem = 0u;
        for (int j = 0; j < 256; j++) {
            unsigned int cj = g_hist[j];
            if (cum + cj >= k) { sel = (unsigned int)j; krem = k - cum; break; }
            cum += cj;
        }
        g_prefix |= sel << shift;
        g_krem    = krem;
    }
    __syncthreads();
    g_hist[threadIdx.x] = 0u;   // launched with 256 threads
}

// ---------------- count / sum of values strictly below threshold ----------------
__global__ void __launch_bounds__(256)
final_pass_kernel()
{
    __shared__ float        sh_sum[8];
    __shared__ unsigned int sh_cnt[8];

    float t = __uint_as_float(g_prefix);
    float        ls = 0.0f;
    unsigned int lc = 0u;

    for (int i = blockIdx.x * blockDim.x + threadIdx.x; i < NTOT;
         i += gridDim.x * blockDim.x)
    {
        float v = g_loss[i];
        if (v < t) { ls += v; lc++; }
    }
    #pragma unroll
    for (int o = 16; o > 0; o >>= 1) {
        ls += __shfl_down_sync(0xffffffffu, ls, o);
        lc += __shfl_down_sync(0xffffffffu, lc, o);
    }
    int wid = threadIdx.x >> 5, lid = threadIdx.x & 31;
    if (lid == 0) { sh_sum[wid] = ls; sh_cnt[wid] = lc; }
    __syncthreads();
    if (threadIdx.x == 0) {
        float ts = 0.0f; unsigned int tc = 0u;
        #pragma unroll
        for (int w = 0; w < 8; w++) { ts += sh_sum[w]; tc += sh_cnt[w]; }
        atomicAdd(&g_sum_less, (double)ts);
        atomicAdd(&g_count_less, tc);
    }
}

// ---------------- finish: assemble scalar ----------------
__global__ void finish_kernel(float* __restrict__ out)
{
    unsigned int n = g_n;
    unsigned int k = n >> 2;
    double t = (double)__uint_as_float(g_prefix);
    double sum_small = g_sum_less + (double)(k - g_count_less) * t;
    long long d = (long long)n - (long long)k;
    if (d < 1) d = 1;
    out[0] = (float)((g_sum_valid - sum_small) / (double)d);
}

// ---------------- launch ----------------
extern "C" void kernel_launch(void* const* d_in, const int* in_sizes, int n_in,
                              void* d_out, int out_size)
{
    const float* pred = (const float*)d_in[0];
    const float* tgt  = (const float*)d_in[1];
    // d_in[2] = mask (already baked into p1/p2/p3; unused)
    const float* intr = (const float*)d_in[3];
    const int*   p1   = (const int*)d_in[4];
    const int*   p2   = (const int*)d_in[5];
    const int*   p3   = (const int*)d_in[6];
    float* out = (float*)d_out;

    init_kernel<<<1, 256>>>();
    compute_kernel<<<592, 256>>>(pred, tgt, intr, p1, p2, p3);
    resolve_kernel<<<1, 256>>>(24, 1);
    hist_pass_kernel<<<296, 256>>>(16);
    resolve_kernel<<<1, 256>>>(16, 0);
    hist_pass_kernel<<<296, 256>>>(8);
    resolve_kernel<<<1, 256>>>(8, 0);
    hist_pass_kernel<<<296, 256>>>(0);
    resolve_kernel<<<1, 256>>>(0, 0);
    final_pass_kernel<<<296, 256>>>();
    finish_kernel<<<1, 1>>>(out);
}